// round 13
// baseline (speedup 1.0000x reference)
#include <cuda_runtime.h>
#include <math.h>

#define NDIM 768
#define FDIM 128
#define HDIM 128
#define NN (NDIM*NDIM)

// scratch (no cudaMalloc allowed)
__device__ float g_Xc[2*2*NDIM*64];   // [b][ch][i][d]

// packed 2xfp32 FMA (sm_100+); bit-identical to two scalar fmaf (RN)
union F2U { float2 f; unsigned long long u; };
__device__ __forceinline__ float2 ffma2(float2 a, float2 b, float2 c) {
    F2U A, B, C, D;
    A.f = a; B.f = b; C.f = c;
    asm("fma.rn.f32x2 %0, %1, %2, %3;" : "=l"(D.u) : "l"(A.u), "l"(B.u), "l"(C.u));
    return D.f;
}

__device__ __forceinline__ void cpa16(void* dst_smem, const void* src) {
    unsigned sa = (unsigned)__cvta_generic_to_shared(dst_smem);
    asm volatile("cp.async.cg.shared.global [%0], [%1], 16;\n" :: "r"(sa), "l"(src));
}
#define CP_COMMIT() asm volatile("cp.async.commit_group;\n" ::: "memory")
#define CP_WAIT(n)  asm volatile("cp.async.wait_group %0;\n" :: "n"(n) : "memory")

// ---------------------------------------------------------------------------
// K1: Xc = Xskip + gate * (relu(X@W1+b1)@W2+b2)   (unchanged — measured best)
// ---------------------------------------------------------------------------
#define PR_ROWS  4
#define PR_CHUNK 32
#define PR_NCH   (FDIM / PR_CHUNK)   // 4

struct PrepSmem {
    __align__(16) float xs[FDIM][PR_ROWS];
    __align__(16) float hs[HDIM][PR_ROWS];
    __align__(16) float ws[2][PR_CHUNK][HDIM];
};

__device__ __forceinline__ float2 prep_layer(
    const float* __restrict__ W, float bias,
    const float (*in)[PR_ROWS], float ws[2][PR_CHUNK][HDIM], int t)
{
    const int h = t & 127;
    const int s = t >> 7;
    float2 acc = make_float2(bias, bias);

    {
        float* dst = &ws[0][0][0];
        #pragma unroll
        for (int it = 0; it < 4; it++) {
            const int idx = (it * 256 + t) * 4;
            cpa16(dst + idx, W + idx);
        }
        CP_COMMIT();
    }

    #pragma unroll
    for (int c = 0; c < PR_NCH; c++) {
        const int buf = c & 1;
        if (c + 1 < PR_NCH) {
            const float* src = W + (size_t)(c + 1) * PR_CHUNK * HDIM;
            float* dst = &ws[(c + 1) & 1][0][0];
            #pragma unroll
            for (int it = 0; it < 4; it++) {
                const int idx = (it * 256 + t) * 4;
                cpa16(dst + idx, src + idx);
            }
            CP_COMMIT();
            CP_WAIT(1);
        } else {
            CP_WAIT(0);
        }
        __syncthreads();

        #pragma unroll
        for (int fi = 0; fi < PR_CHUNK; fi++) {
            const int f = c * PR_CHUNK + fi;
            const float w = ws[buf][fi][h];
            const float2 xv = *(const float2*)&in[f][2 * s];
            acc = ffma2(xv, make_float2(w, w), acc);
        }
        __syncthreads();
    }
    return acc;
}

__global__ __launch_bounds__(256) void k_prep(
    const float* __restrict__ X,
    const float* __restrict__ w1, const float* __restrict__ b1,
    const float* __restrict__ w2, const float* __restrict__ b2,
    const float* __restrict__ gate)
{
    __shared__ PrepSmem sm;
    const int t = threadIdx.x;
    const int h = t & 127;
    const int s = t >> 7;
    const int row0 = blockIdx.x * PR_ROWS;
    const float g = gate[0];

    {
        const int f = t & 127;
        const int r0 = (t >> 7) * 2;
        sm.xs[f][r0]     = X[(size_t)(row0 + r0) * FDIM + f];
        sm.xs[f][r0 + 1] = X[(size_t)(row0 + r0 + 1) * FDIM + f];
    }

    float2 a1 = prep_layer(w1, b1[h], sm.xs, sm.ws, t);
    sm.hs[h][2 * s]     = fmaxf(a1.x, 0.0f);
    sm.hs[h][2 * s + 1] = fmaxf(a1.y, 0.0f);
    __syncthreads();

    float2 a2 = prep_layer(w2, b2[h], sm.hs, sm.ws, t);

    const int b  = row0 / NDIM;
    const int ch = h & 1;
    const int d  = h >> 1;
    const int i0 = (row0 % NDIM) + 2 * s;
    float* dst = g_Xc + ((size_t)(b * 2 + ch) * NDIM + i0) * 64 + d;
    dst[0]  = sm.xs[h][2 * s]     + g * a2.x;
    dst[64] = sm.xs[h][2 * s + 1] + g * a2.y;
}

// ---------------------------------------------------------------------------
// K2 (fused): 64x32 upper tile, 512 threads, 312 blocks (R9 grid — best).
// Gram with i-packed accumulators + pre-duplicated B in smem (no dup MOVs);
// MLP with float4 weight LDS.128; relu via scalar fmaxf (FMNMX, alu pipe).
// ---------------------------------------------------------------------------
#define AS_STRIDE 68
#define BD_STRIDE 68
#define AS_BYTES (64*AS_STRIDE*4)        // 17408
#define BD_BYTES (64*BD_STRIDE*4)        // 17408
#define FUSED_SMEM (2*AS_BYTES + 2*BD_BYTES)  // 69632

__global__ __launch_bounds__(512, 2) void k_fused(
    const float* __restrict__ sw1, const float* __restrict__ sb1,
    const float* __restrict__ sw2, const float* __restrict__ sb2,
    const float* __restrict__ gumbel, float* __restrict__ out)
{
    extern __shared__ char dynsm[];
    float (*As0)[AS_STRIDE] = (float(*)[AS_STRIDE])(dynsm);
    float (*As1)[AS_STRIDE] = (float(*)[AS_STRIDE])(dynsm + AS_BYTES);
    float (*Bd0)[BD_STRIDE] = (float(*)[BD_STRIDE])(dynsm + 2*AS_BYTES);           // (v,v) dup
    float (*Bd1)[BD_STRIDE] = (float(*)[BD_STRIDE])(dynsm + 2*AS_BYTES + BD_BYTES);
    float (*vt)[33]         = (float(*)[33])(dynsm + 2*AS_BYTES);  // overlays Bd

    __shared__ __align__(16) float4 wab4[HDIM];  // (a,a,b,b)
    __shared__ __align__(16) float4 wcd4[HDIM];  // (c,c,w,w)

    const int t = threadIdx.x;

    // tile decode (batch, 64-row block bi, 32-col strip bj2)
    int idx = blockIdx.x;
    int b = 0;
    if (idx >= 156) { b = 1; idx -= 156; }
    int bi = 0;
    while (idx >= 24 - 2 * bi) { idx -= 24 - 2 * bi; bi++; }
    const int bj2 = 2 * bi + idx;
    const int i0 = bi * 64;
    const int j0 = bj2 * 32;
    const bool diag = (bj2 <= 2 * bi + 1);

    // stage score-MLP weights (float4-packed)
    if (t < HDIM) {
        const float a  = sw1[t];
        const float bb = sw1[HDIM + t];
        const float c  = sb1[t];
        const float w  = sw2[t * 2 + 1] - sw2[t * 2];
        wab4[t] = make_float4(a, a, bb, bb);
        wcd4[t] = make_float4(c, c, w, w);
    }

    // stage Xc tiles: A natural, B duplicated (v,v)
    const size_t choff = (size_t)NDIM * 64;
    const float* X0 = g_Xc + (size_t)b * 2 * choff;
    const float* X1 = X0 + choff;
    #pragma unroll
    for (int k = t; k < 64 * 64; k += 512) {
        const int i = k >> 6, d = k & 63;
        const size_t off = (size_t)(i0 + i) * 64 + d;
        As0[d][i] = X0[off];
        As1[d][i] = X1[off];
    }
    #pragma unroll
    for (int k = t; k < 32 * 64; k += 512) {
        const int d = k >> 5, j = k & 31;
        const size_t off = (size_t)(j0 + j) * 64 + d;
        const float v0 = X0[off];
        const float v1 = X1[off];
        *(float2*)&Bd0[d][2 * j] = make_float2(v0, v0);
        *(float2*)&Bd1[d][2 * j] = make_float2(v1, v1);
    }
    __syncthreads();

    // gram: thread owns i-pair (ty*2, +1) x j-pair (tx*2, +1)
    // accumulators i-packed: p0[jj] = (P_ch0(i,j_jj), P_ch0(i+1,j_jj))
    const int tx = t & 15;
    const int ty = t >> 4;
    float2 p0[2], p1[2];
    p0[0] = make_float2(0.f, 0.f); p0[1] = make_float2(0.f, 0.f);
    p1[0] = make_float2(0.f, 0.f); p1[1] = make_float2(0.f, 0.f);

    #pragma unroll 16
    for (int d = 0; d < 64; d++) {
        const float2 av0 = *(const float2*)&As0[d][ty * 2];
        const float2 av1 = *(const float2*)&As1[d][ty * 2];
        const float4 bq0 = *(const float4*)&Bd0[d][tx * 4];  // (BjA,BjA,BjB,BjB)
        const float4 bq1 = *(const float4*)&Bd1[d][tx * 4];
        p0[0] = ffma2(av0, make_float2(bq0.x, bq0.y), p0[0]);
        p0[1] = ffma2(av0, make_float2(bq0.z, bq0.w), p0[1]);
        p1[0] = ffma2(av1, make_float2(bq1.x, bq1.y), p1[0]);
        p1[1] = ffma2(av1, make_float2(bq1.z, bq1.w), p1[1]);
    }
    __syncthreads();   // all Bd reads done (vt overlays Bd)

    // edge MLP: acc[jj] lanes = edges (i,j_jj),(i+1,j_jj)
    float2 acc[2];
    acc[0] = make_float2(0.0f, 0.0f);
    acc[1] = make_float2(0.0f, 0.0f);

    #pragma unroll 8
    for (int h = 0; h < HDIM; h++) {
        const float4 qab = wab4[h];
        const float4 qcd = wcd4[h];
        const float2 a2 = make_float2(qab.x, qab.y);
        const float2 b2 = make_float2(qab.z, qab.w);
        const float2 c2 = make_float2(qcd.x, qcd.y);
        const float2 w2 = make_float2(qcd.z, qcd.w);
        #pragma unroll
        for (int jj = 0; jj < 2; jj++) {
            float2 pre = ffma2(a2, p0[jj], ffma2(b2, p1[jj], c2));
            pre.x = fmaxf(pre.x, 0.0f);
            pre.y = fmaxf(pre.y, 0.0f);
            acc[jj] = ffma2(w2, pre, acc[jj]);
        }
    }

    const float bd = sb2[1] - sb2[0];
    const float* G = gumbel + (size_t)b * NN * 2;
    float* O = out + (size_t)b * NN;

    const int gi = i0 + ty * 2;
    const int gj = j0 + tx * 2;

    if (!diag) {
        // gumbel rows for the two i's (each float4 covers j, j+1)
        const float4 g4a = *(const float4*)&G[((size_t)gi * NDIM + gj) * 2];
        const float4 g4b = *(const float4*)&G[((size_t)(gi + 1) * NDIM + gj) * 2];
        const float vAA = ((acc[0].x + bd) + (g4a.y - g4a.x) > 0.0f) ? 1.0f : 0.0f;
        const float vBA = ((acc[0].y + bd) + (g4b.y - g4b.x) > 0.0f) ? 1.0f : 0.0f;
        const float vAB = ((acc[1].x + bd) + (g4a.w - g4a.z) > 0.0f) ? 1.0f : 0.0f;
        const float vBB = ((acc[1].y + bd) + (g4b.w - g4b.z) > 0.0f) ? 1.0f : 0.0f;
        vt[ty * 2][tx * 2]         = vAA;
        vt[ty * 2 + 1][tx * 2]     = vBA;
        vt[ty * 2][tx * 2 + 1]     = vAB;
        vt[ty * 2 + 1][tx * 2 + 1] = vBB;
        __syncthreads();

        // row writes: 64 rows x 32 floats (1 float4 per thread)
        {
            const int row = t >> 3;
            const int q   = t & 7;
            float tmp[4];
            #pragma unroll
            for (int k = 0; k < 4; k++) tmp[k] = vt[row][q * 4 + k];
            float* dst = O + (size_t)(i0 + row) * NDIM + j0 + q * 4;
            *(float4*)dst = make_float4(tmp[0], tmp[1], tmp[2], tmp[3]);
        }
        // mirror writes: 32 rows x 64 floats (1 float4 per thread)
        {
            const int row = t >> 4;
            const int oct = t & 15;
            float tmp[4];
            #pragma unroll
            for (int k = 0; k < 4; k++) tmp[k] = vt[oct * 4 + k][row];
            float* dst = O + (size_t)(j0 + row) * NDIM + i0 + oct * 4;
            *(float4*)dst = make_float4(tmp[0], tmp[1], tmp[2], tmp[3]);
        }
    } else {
        // diagonal-overlap strip: predicated scatter, each cell written once
        #pragma unroll
        for (int c = 0; c < 2; c++) {          // i offset
            const int gic = gi + c;
            const float4 g4 = *(const float4*)&G[((size_t)gic * NDIM + gj) * 2];
            #pragma unroll
            for (int a = 0; a < 2; a++) {      // j offset
                const int gjc = gj + a;
                const float accv = a ? (c ? acc[1].y : acc[1].x)
                                     : (c ? acc[0].y : acc[0].x);
                const float gg0 = a ? g4.z : g4.x;
                const float gg1 = a ? g4.w : g4.y;
                const float v = ((accv + bd) + (gg1 - gg0) > 0.0f) ? 1.0f : 0.0f;
                if (gjc > gic) {
                    O[(size_t)gic * NDIM + gjc] = v;
                    O[(size_t)gjc * NDIM + gic] = v;
                } else if (gjc == gic) {
                    O[(size_t)gic * NDIM + gic] = 0.0f;
                }
            }
        }
    }
}

// ---------------------------------------------------------------------------
extern "C" void kernel_launch(void* const* d_in, const int* in_sizes, int n_in,
                              void* d_out, int out_size)
{
    const float* X     = (const float*)d_in[0];
    const float* ef_w1 = (const float*)d_in[1];
    const float* ef_b1 = (const float*)d_in[2];
    const float* ef_w2 = (const float*)d_in[3];
    const float* ef_b2 = (const float*)d_in[4];
    const float* gate  = (const float*)d_in[5];
    const float* sm_w1 = (const float*)d_in[6];
    const float* sm_b1 = (const float*)d_in[7];
    const float* sm_w2 = (const float*)d_in[8];
    const float* sm_b2 = (const float*)d_in[9];
    const float* gumb  = (const float*)d_in[10];
    float* out = (float*)d_out;

    cudaFuncSetAttribute(k_fused, cudaFuncAttributeMaxDynamicSharedMemorySize, FUSED_SMEM);

    k_prep<<<384, 256>>>(X, ef_w1, ef_b1, ef_w2, ef_b2, gate);
    k_fused<<<312, 512, FUSED_SMEM>>>(sm_w1, sm_b1, sm_w2, sm_b2, gumb, out);
}

// round 14
// speedup vs baseline: 1.2721x; 1.2721x over previous
#include <cuda_runtime.h>
#include <math.h>

#define NDIM 768
#define FDIM 128
#define HDIM 128
#define NN (NDIM*NDIM)

// scratch (no cudaMalloc allowed)
__device__ float g_Xc[2*2*NDIM*64];   // [b][ch][i][d]

// packed 2xfp32 FMA (sm_100+); bit-identical to two scalar fmaf (RN)
union F2U { float2 f; unsigned long long u; };
__device__ __forceinline__ float2 ffma2(float2 a, float2 b, float2 c) {
    F2U A, B, C, D;
    A.f = a; B.f = b; C.f = c;
    asm("fma.rn.f32x2 %0, %1, %2, %3;" : "=l"(D.u) : "l"(A.u), "l"(B.u), "l"(C.u));
    return D.f;
}

__device__ __forceinline__ void cpa16(void* dst_smem, const void* src) {
    unsigned sa = (unsigned)__cvta_generic_to_shared(dst_smem);
    asm volatile("cp.async.cg.shared.global [%0], [%1], 16;\n" :: "r"(sa), "l"(src));
}
#define CP_COMMIT() asm volatile("cp.async.commit_group;\n" ::: "memory")
#define CP_WAIT(n)  asm volatile("cp.async.wait_group %0;\n" :: "n"(n) : "memory")

// ---------------------------------------------------------------------------
// K1: Xc = Xskip + gate * (relu(X@W1+b1)@W2+b2)   (unchanged — measured best)
// ---------------------------------------------------------------------------
#define PR_ROWS  4
#define PR_CHUNK 32
#define PR_NCH   (FDIM / PR_CHUNK)   // 4

struct PrepSmem {
    __align__(16) float xs[FDIM][PR_ROWS];
    __align__(16) float hs[HDIM][PR_ROWS];
    __align__(16) float ws[2][PR_CHUNK][HDIM];
};

__device__ __forceinline__ float2 prep_layer(
    const float* __restrict__ W, float bias,
    const float (*in)[PR_ROWS], float ws[2][PR_CHUNK][HDIM], int t)
{
    const int h = t & 127;
    const int s = t >> 7;
    float2 acc = make_float2(bias, bias);

    {
        float* dst = &ws[0][0][0];
        #pragma unroll
        for (int it = 0; it < 4; it++) {
            const int idx = (it * 256 + t) * 4;
            cpa16(dst + idx, W + idx);
        }
        CP_COMMIT();
    }

    #pragma unroll
    for (int c = 0; c < PR_NCH; c++) {
        const int buf = c & 1;
        if (c + 1 < PR_NCH) {
            const float* src = W + (size_t)(c + 1) * PR_CHUNK * HDIM;
            float* dst = &ws[(c + 1) & 1][0][0];
            #pragma unroll
            for (int it = 0; it < 4; it++) {
                const int idx = (it * 256 + t) * 4;
                cpa16(dst + idx, src + idx);
            }
            CP_COMMIT();
            CP_WAIT(1);
        } else {
            CP_WAIT(0);
        }
        __syncthreads();

        #pragma unroll
        for (int fi = 0; fi < PR_CHUNK; fi++) {
            const int f = c * PR_CHUNK + fi;
            const float w = ws[buf][fi][h];
            const float2 xv = *(const float2*)&in[f][2 * s];
            acc = ffma2(xv, make_float2(w, w), acc);
        }
        __syncthreads();
    }
    return acc;
}

__global__ __launch_bounds__(256) void k_prep(
    const float* __restrict__ X,
    const float* __restrict__ w1, const float* __restrict__ b1,
    const float* __restrict__ w2, const float* __restrict__ b2,
    const float* __restrict__ gate)
{
    __shared__ PrepSmem sm;
    const int t = threadIdx.x;
    const int h = t & 127;
    const int s = t >> 7;
    const int row0 = blockIdx.x * PR_ROWS;
    const float g = gate[0];

    {
        const int f = t & 127;
        const int r0 = (t >> 7) * 2;
        sm.xs[f][r0]     = X[(size_t)(row0 + r0) * FDIM + f];
        sm.xs[f][r0 + 1] = X[(size_t)(row0 + r0 + 1) * FDIM + f];
    }

    float2 a1 = prep_layer(w1, b1[h], sm.xs, sm.ws, t);
    sm.hs[h][2 * s]     = fmaxf(a1.x, 0.0f);
    sm.hs[h][2 * s + 1] = fmaxf(a1.y, 0.0f);
    __syncthreads();

    float2 a2 = prep_layer(w2, b2[h], sm.hs, sm.ws, t);

    const int b  = row0 / NDIM;
    const int ch = h & 1;
    const int d  = h >> 1;
    const int i0 = (row0 % NDIM) + 2 * s;
    float* dst = g_Xc + ((size_t)(b * 2 + ch) * NDIM + i0) * 64 + d;
    dst[0]  = sm.xs[h][2 * s]     + g * a2.x;
    dst[64] = sm.xs[h][2 * s + 1] + g * a2.y;
}

// ---------------------------------------------------------------------------
// K2 (fused): R9 kernel verbatim EXCEPT the MLP weight loads:
// 4 broadcast LDS.64 per h -> 2 broadcast LDS.128 per h (float4 packing,
// aligned halves feed FFMA2 directly, zero MOVs).
// 312 blocks x 512 threads, 2 blocks/SM.
// ---------------------------------------------------------------------------
#define AS_STRIDE 68
#define BS_STRIDE 34
#define AS_BYTES (64*AS_STRIDE*4)        // 17408
#define BS_BYTES (64*BS_STRIDE*4)        // 8704
#define FUSED_SMEM (2*AS_BYTES + 2*BS_BYTES)  // 52224

__global__ __launch_bounds__(512, 2) void k_fused(
    const float* __restrict__ sw1, const float* __restrict__ sb1,
    const float* __restrict__ sw2, const float* __restrict__ sb2,
    const float* __restrict__ gumbel, float* __restrict__ out)
{
    extern __shared__ char dynsm[];
    float (*As0)[AS_STRIDE] = (float(*)[AS_STRIDE])(dynsm);
    float (*As1)[AS_STRIDE] = (float(*)[AS_STRIDE])(dynsm + AS_BYTES);
    float (*Bs0)[BS_STRIDE] = (float(*)[BS_STRIDE])(dynsm + 2*AS_BYTES);
    float (*Bs1)[BS_STRIDE] = (float(*)[BS_STRIDE])(dynsm + 2*AS_BYTES + BS_BYTES);
    float (*vt)[33]         = (float(*)[33])(dynsm + 2*AS_BYTES);  // overlays Bs

    __shared__ __align__(16) float4 wab4[HDIM];  // (a,a,b,b)
    __shared__ __align__(16) float4 wcd4[HDIM];  // (c,c,w,w)

    const int t = threadIdx.x;

    // tile decode (batch, 64-row block bi, 32-col strip bj2)
    int idx = blockIdx.x;
    int b = 0;
    if (idx >= 156) { b = 1; idx -= 156; }
    int bi = 0;
    while (idx >= 24 - 2 * bi) { idx -= 24 - 2 * bi; bi++; }
    const int bj2 = 2 * bi + idx;
    const int i0 = bi * 64;
    const int j0 = bj2 * 32;
    const bool diag = (bj2 <= 2 * bi + 1);

    // stage score-MLP weights (float4-packed, broadcast-read in MLP loop)
    if (t < HDIM) {
        const float a  = sw1[t];
        const float bb = sw1[HDIM + t];
        const float c  = sb1[t];
        const float w  = sw2[t * 2 + 1] - sw2[t * 2];
        wab4[t] = make_float4(a, a, bb, bb);
        wcd4[t] = make_float4(c, c, w, w);
    }

    // stage Xc tiles, channels separate (R9 layout, coalesced)
    const size_t choff = (size_t)NDIM * 64;
    const float* X0 = g_Xc + (size_t)b * 2 * choff;
    const float* X1 = X0 + choff;
    #pragma unroll
    for (int k = t; k < 64 * 64; k += 512) {
        const int i = k >> 6, d = k & 63;
        const size_t off = (size_t)(i0 + i) * 64 + d;
        As0[d][i] = X0[off];
        As1[d][i] = X1[off];
    }
    #pragma unroll
    for (int k = t; k < 32 * 64; k += 512) {
        const int j = k >> 6, d = k & 63;
        const size_t off = (size_t)(j0 + j) * 64 + d;
        Bs0[d][j] = X0[off];
        Bs1[d][j] = X1[off];
    }
    __syncthreads();

    // gram: micro-tile 2i x 2j per thread, j-packed float2 per channel (R9)
    const int tx = t & 15;   // j pair: j0 + tx*2 + {0,1}
    const int ty = t >> 4;   // i pair: i0 + ty*2 + {0,1}
    float2 p0[2], p1[2];
    #pragma unroll
    for (int a = 0; a < 2; a++) { p0[a] = make_float2(0.f, 0.f); p1[a] = make_float2(0.f, 0.f); }

    #pragma unroll 16
    for (int d = 0; d < 64; d++) {
        const float2 a0 = *(const float2*)&As0[d][ty * 2];
        const float2 a1 = *(const float2*)&As1[d][ty * 2];
        const float2 b0 = *(const float2*)&Bs0[d][tx * 2];
        const float2 b1 = *(const float2*)&Bs1[d][tx * 2];
        p0[0] = ffma2(make_float2(a0.x, a0.x), b0, p0[0]);
        p0[1] = ffma2(make_float2(a0.y, a0.y), b0, p0[1]);
        p1[0] = ffma2(make_float2(a1.x, a1.x), b1, p1[0]);
        p1[1] = ffma2(make_float2(a1.y, a1.y), b1, p1[1]);
    }
    __syncthreads();   // all Bs reads done (vt overlays Bs)

    // edge MLP (identical op order to R9; weights via 2 LDS.128 per h)
    float2 acc[2];
    acc[0] = make_float2(0.0f, 0.0f);
    acc[1] = make_float2(0.0f, 0.0f);

    #pragma unroll 8
    for (int h = 0; h < HDIM; h++) {
        const float4 qab = wab4[h];
        const float4 qcd = wcd4[h];
        const float2 a2 = make_float2(qab.x, qab.y);
        const float2 b2 = make_float2(qab.z, qab.w);
        const float2 c2 = make_float2(qcd.x, qcd.y);
        const float2 w2 = make_float2(qcd.z, qcd.w);
        #pragma unroll
        for (int a = 0; a < 2; a++) {
            float2 pre = ffma2(a2, p0[a], ffma2(b2, p1[a], c2));
            pre.x = fmaxf(pre.x, 0.0f);
            pre.y = fmaxf(pre.y, 0.0f);
            acc[a] = ffma2(w2, pre, acc[a]);
        }
    }

    const float bd = sb2[1] - sb2[0];
    const float* G = gumbel + (size_t)b * NN * 2;
    float* O = out + (size_t)b * NN;

    if (!diag) {
        #pragma unroll
        for (int a = 0; a < 2; a++) {
            const int gi = i0 + ty * 2 + a;
            const float4 g4 = *(const float4*)&G[((size_t)gi * NDIM + j0 + tx * 2) * 2];
            const float v0 = ((acc[a].x + bd) + (g4.y - g4.x) > 0.0f) ? 1.0f : 0.0f;
            const float v1 = ((acc[a].y + bd) + (g4.w - g4.z) > 0.0f) ? 1.0f : 0.0f;
            vt[ty * 2 + a][tx * 2]     = v0;
            vt[ty * 2 + a][tx * 2 + 1] = v1;
        }
        __syncthreads();

        // row writes: 64 rows x 32 floats (1 float4 per thread)
        {
            const int row = t >> 3;
            const int q   = t & 7;
            float tmp[4];
            #pragma unroll
            for (int k = 0; k < 4; k++) tmp[k] = vt[row][q * 4 + k];
            float* dst = O + (size_t)(i0 + row) * NDIM + j0 + q * 4;
            *(float4*)dst = make_float4(tmp[0], tmp[1], tmp[2], tmp[3]);
        }
        // mirror writes: 32 rows x 64 floats (1 float4 per thread)
        {
            const int row = t >> 4;
            const int oct = t & 15;
            float tmp[4];
            #pragma unroll
            for (int k = 0; k < 4; k++) tmp[k] = vt[oct * 4 + k][row];
            float* dst = O + (size_t)(j0 + row) * NDIM + i0 + oct * 4;
            *(float4*)dst = make_float4(tmp[0], tmp[1], tmp[2], tmp[3]);
        }
    } else {
        // diagonal-overlap strip: predicated scatter, each cell written once
        #pragma unroll
        for (int a = 0; a < 2; a++) {
            const int gi = i0 + ty * 2 + a;
            const float4 g4 = *(const float4*)&G[((size_t)gi * NDIM + j0 + tx * 2) * 2];
            #pragma unroll
            for (int c = 0; c < 2; c++) {
                const int gj = j0 + tx * 2 + c;
                const float accv = c ? acc[a].y : acc[a].x;
                const float gg0 = c ? g4.z : g4.x;
                const float gg1 = c ? g4.w : g4.y;
                const float v = ((accv + bd) + (gg1 - gg0) > 0.0f) ? 1.0f : 0.0f;
                if (gj > gi) {
                    O[(size_t)gi * NDIM + gj] = v;
                    O[(size_t)gj * NDIM + gi] = v;
                } else if (gj == gi) {
                    O[(size_t)gi * NDIM + gi] = 0.0f;
                }
            }
        }
    }
}

// ---------------------------------------------------------------------------
extern "C" void kernel_launch(void* const* d_in, const int* in_sizes, int n_in,
                              void* d_out, int out_size)
{
    const float* X     = (const float*)d_in[0];
    const float* ef_w1 = (const float*)d_in[1];
    const float* ef_b1 = (const float*)d_in[2];
    const float* ef_w2 = (const float*)d_in[3];
    const float* ef_b2 = (const float*)d_in[4];
    const float* gate  = (const float*)d_in[5];
    const float* sm_w1 = (const float*)d_in[6];
    const float* sm_b1 = (const float*)d_in[7];
    const float* sm_w2 = (const float*)d_in[8];
    const float* sm_b2 = (const float*)d_in[9];
    const float* gumb  = (const float*)d_in[10];
    float* out = (float*)d_out;

    cudaFuncSetAttribute(k_fused, cudaFuncAttributeMaxDynamicSharedMemorySize, FUSED_SMEM);

    k_prep<<<384, 256>>>(X, ef_w1, ef_b1, ef_w2, ef_b2, gate);
    k_fused<<<312, 512, FUSED_SMEM>>>(sm_w1, sm_b1, sm_w2, sm_b2, gumb, out);
}